// round 1
// baseline (speedup 1.0000x reference)
#include <cuda_runtime.h>

#define THREADS 512
#define WARPS (THREADS / 32)
#define RANK 8
#define NR_MAX 4          // max rows per warp (8192 rows / (152*16) warps ~ 3.4)
#define LORA_SCALE 2.0f   // alpha/r = 16/8

// Fused LoRA: out[row][n] = scale * sum_j ( sum_k x[row][k]*A[k][j] ) * B[j][n]
// One CTA per SM. Shared buffer holds A (phase 1) then B*scale (phase 2).
__global__ __launch_bounds__(THREADS, 1)
void lora_fused_kernel(const float* __restrict__ x,
                       const float* __restrict__ A,
                       const float* __restrict__ Bm,
                       float* __restrict__ out,
                       int rows, int K, int N, int warps_total)
{
    extern __shared__ float4 s4[];   // max(K, N) * RANK floats = 128 KB
    const int tid  = threadIdx.x;
    const int lane = tid & 31;
    const int warp = tid >> 5;

    // ---------------- Phase 0: stage A [K][RANK] into shared ----------------
    const float4* A4 = reinterpret_cast<const float4*>(A);
    const int a4_elems = (K * RANK) >> 2;            // 8192 float4
    for (int i = tid; i < a4_elems; i += THREADS) s4[i] = A4[i];
    __syncthreads();

    // Balanced row split across every warp in the grid.
    const long W  = (long)blockIdx.x * WARPS + warp;
    const int  r0 = (int)((W * (long)rows) / warps_total);
    const int  r1 = (int)(((W + 1) * (long)rows) / warps_total);
    const int  nr = r1 - r0;                         // 3 or 4

    float acc[NR_MAX][RANK];
#pragma unroll
    for (int r = 0; r < NR_MAX; r++)
#pragma unroll
        for (int j = 0; j < RANK; j++) acc[r][j] = 0.0f;

    // ---------------- Phase 1: t = x @ A (per-warp, multi-row) ----------------
    const int K4 = K >> 2;                           // 1024
    const float4* x4 = reinterpret_cast<const float4*>(x);

    for (int i = lane; i < K4; i += 32) {
        // A rows for k = 4i..4i+3 : 32 contiguous floats (reused across rows)
        float a[32];
#pragma unroll
        for (int q = 0; q < 8; q++)
            *reinterpret_cast<float4*>(&a[q * 4]) = s4[i * 8 + q];

#pragma unroll
        for (int r = 0; r < NR_MAX; r++) {
            if (r < nr) {
                float4 xv = x4[(size_t)(r0 + r) * K4 + i];   // coalesced LDG.128
                const float xc[4] = {xv.x, xv.y, xv.z, xv.w};
#pragma unroll
                for (int c = 0; c < 4; c++)
#pragma unroll
                    for (int j = 0; j < RANK; j++)
                        acc[r][j] = fmaf(xc[c], a[c * RANK + j], acc[r][j]);
            }
        }
    }

    // Warp butterfly all-reduce: every lane ends with the full t values.
#pragma unroll
    for (int off = 16; off > 0; off >>= 1) {
#pragma unroll
        for (int r = 0; r < NR_MAX; r++)
#pragma unroll
            for (int j = 0; j < RANK; j++)
                acc[r][j] += __shfl_xor_sync(0xffffffffu, acc[r][j], off);
    }

    __syncthreads();   // everyone done reading A from shared

    // ---------------- Phase 0b: stage B*scale [RANK][N] into shared ----------
    const float4* B4 = reinterpret_cast<const float4*>(Bm);
    const int b4_elems = (RANK * N) >> 2;            // 8192 float4
    for (int i = tid; i < b4_elems; i += THREADS) {
        float4 v = B4[i];
        v.x *= LORA_SCALE; v.y *= LORA_SCALE; v.z *= LORA_SCALE; v.w *= LORA_SCALE;
        s4[i] = v;
    }
    __syncthreads();

    // ---------------- Phase 2: out = t @ (B*scale) ----------------
    const int N4 = N >> 2;                           // 1024
    float4* out4 = reinterpret_cast<float4*>(out);

    for (int i = lane; i < N4; i += 32) {
        float4 b[RANK];                              // B column block, reused across rows
#pragma unroll
        for (int j = 0; j < RANK; j++) b[j] = s4[j * N4 + i];

#pragma unroll
        for (int r = 0; r < NR_MAX; r++) {
            if (r < nr) {
                float4 o = make_float4(0.f, 0.f, 0.f, 0.f);
#pragma unroll
                for (int j = 0; j < RANK; j++) {
                    o.x = fmaf(acc[r][j], b[j].x, o.x);
                    o.y = fmaf(acc[r][j], b[j].y, o.y);
                    o.z = fmaf(acc[r][j], b[j].z, o.z);
                    o.w = fmaf(acc[r][j], b[j].w, o.w);
                }
                out4[(size_t)(r0 + r) * N4 + i] = o;  // coalesced STG.128
            }
        }
    }
}

extern "C" void kernel_launch(void* const* d_in, const int* in_sizes, int n_in,
                              void* d_out, int out_size)
{
    const float* x  = (const float*)d_in[0];   // [4,2048,4096]
    const float* A  = (const float*)d_in[1];   // [4096,8]
    const float* Bm = (const float*)d_in[2];   // [8,4096]
    float* out = (float*)d_out;

    const int K    = in_sizes[1] / RANK;       // 4096
    const int N    = in_sizes[2] / RANK;       // 4096
    const int rows = in_sizes[0] / K;          // 8192

    int sms = 148;
    cudaDeviceGetAttribute(&sms, cudaDevAttrMultiProcessorCount, 0);
    const int grid = sms;
    const int warps_total = grid * WARPS;

    const int smem = ((K > N ? K : N) * RANK) * (int)sizeof(float);  // 131072 B
    cudaFuncSetAttribute(lora_fused_kernel,
                         cudaFuncAttributeMaxDynamicSharedMemorySize, smem);

    lora_fused_kernel<<<grid, THREADS, smem>>>(x, A, Bm, out, rows, K, N, warps_total);
}

// round 2
// speedup vs baseline: 1.9256x; 1.9256x over previous
#include <cuda_runtime.h>
#include <cstdint>

#define THREADS 512
#define RANK 8
#define K4 1024            // K/4 = 4096/4
#define N4 1024            // N/4
#define MAXROWS 64         // max rows per CTA (8192/152 ~ 54)
#define LORA_SCALE 2.0f    // alpha/r = 16/8

// ---- packed f32x2 helpers (FFMA2 is only reachable via PTX) ----
__device__ __forceinline__ uint64_t pack2(float lo, float hi) {
    uint64_t r; asm("mov.b64 %0, {%1, %2};" : "=l"(r) : "f"(lo), "f"(hi)); return r;
}
__device__ __forceinline__ void unpack2(uint64_t v, float& lo, float& hi) {
    asm("mov.b64 {%0, %1}, %2;" : "=f"(lo), "=f"(hi) : "l"(v));
}
__device__ __forceinline__ uint64_t fma2(uint64_t a, uint64_t b, uint64_t c) {
    uint64_t d; asm("fma.rn.f32x2 %0, %1, %2, %3;" : "=l"(d) : "l"(a), "l"(b), "l"(c)); return d;
}

__global__ __launch_bounds__(THREADS, 1)
void lora_fused_kernel(const float4* __restrict__ x4,
                       const float4* __restrict__ A4,
                       const float4* __restrict__ B4,
                       float4* __restrict__ out4,
                       int rows, int grid)
{
    __shared__ float s_part[MAXROWS * 128];   // [row][warp16][j8] per-warp partials (32 KB)
    __shared__ float s_t[MAXROWS * RANK];     // reduced t (2 KB)

    const int tid  = threadIdx.x;
    const int lane = tid & 31;
    const int warp = tid >> 5;

    const int r0 = (int)((long)blockIdx.x * rows / grid);
    const int r1 = (int)((long)(blockIdx.x + 1) * rows / grid);
    const int nr = r1 - r0;                   // <= MAXROWS

    const int c0 = tid;                       // this thread's two k/n float4 chunks
    const int c1 = tid + THREADS;

    // ---------------- A cache: 2 chunks x 4 k x 8 j, packed as f32x2 pairs ----
    uint64_t a2[2][4][4];
#pragma unroll
    for (int ch = 0; ch < 2; ch++) {
        const int c = ch ? c1 : c0;
#pragma unroll
        for (int kk = 0; kk < 4; kk++) {
            float4 lo = A4[c * 8 + kk * 2];       // A[4c+kk][0..3]
            float4 hi = A4[c * 8 + kk * 2 + 1];   // A[4c+kk][4..7]
            a2[ch][kk][0] = pack2(lo.x, lo.y);
            a2[ch][kk][1] = pack2(lo.z, lo.w);
            a2[ch][kk][2] = pack2(hi.x, hi.y);
            a2[ch][kk][3] = pack2(hi.z, hi.w);
        }
    }

    // ---------------- Phase 1: per-row partial t, folding warp reduce ---------
    const int j_mine = ((lane >> 4) & 1) * 4 + ((lane >> 3) & 1) * 2 + ((lane >> 2) & 1);
    const bool write_lane = (lane & 3) == 0;

    for (int r = 0; r < nr; r++) {
        uint64_t p2[4] = {0ull, 0ull, 0ull, 0ull};
        const size_t xbase = (size_t)(r0 + r) * K4;
#pragma unroll
        for (int ch = 0; ch < 2; ch++) {
            float4 xv = x4[xbase + (ch ? c1 : c0)];    // coalesced LDG.128
            const float xc[4] = {xv.x, xv.y, xv.z, xv.w};
#pragma unroll
            for (int kk = 0; kk < 4; kk++) {
                uint64_t xs = pack2(xc[kk], xc[kk]);
#pragma unroll
                for (int jp = 0; jp < 4; jp++)
                    p2[jp] = fma2(xs, a2[ch][kk][jp], p2[jp]);
            }
        }
        float p[8];
#pragma unroll
        for (int jp = 0; jp < 4; jp++) unpack2(p2[jp], p[2 * jp], p[2 * jp + 1]);

        // Folding butterfly: 9 shfl total instead of 40.
        const bool h = (lane & 16) != 0;
        float q[4];
#pragma unroll
        for (int m = 0; m < 4; m++) {
            float send = h ? p[m] : p[m + 4];
            float keep = h ? p[m + 4] : p[m];
            q[m] = keep + __shfl_xor_sync(0xffffffffu, send, 16);
        }
        const bool qb = (lane & 8) != 0;
        float u[2];
#pragma unroll
        for (int m = 0; m < 2; m++) {
            float send = qb ? q[m] : q[m + 2];
            float keep = qb ? q[m + 2] : q[m];
            u[m] = keep + __shfl_xor_sync(0xffffffffu, send, 8);
        }
        const bool ob = (lane & 4) != 0;
        {
            float send = ob ? u[0] : u[1];
            float keep = ob ? u[1] : u[0];
            float w = keep + __shfl_xor_sync(0xffffffffu, send, 4);
            w += __shfl_xor_sync(0xffffffffu, w, 2);
            w += __shfl_xor_sync(0xffffffffu, w, 1);
            if (write_lane) s_part[r * 128 + warp * 8 + j_mine] = w;
        }
    }
    __syncthreads();

    // ---------------- Cross-warp reduce into s_t ------------------------------
    for (int i = tid; i < nr * RANK; i += THREADS) {
        const int row = i >> 3, j = i & 7;
        float s = 0.0f;
#pragma unroll
        for (int w = 0; w < 16; w++) s += s_part[row * 128 + w * 8 + j];
        s_t[i] = s;
    }
    __syncthreads();

    // ---------------- B cache: 2 chunks x 8 j x (2 n-pairs), pre-scaled -------
    uint64_t b2[2][8][2];
#pragma unroll
    for (int ch = 0; ch < 2; ch++) {
        const int c = ch ? c1 : c0;
#pragma unroll
        for (int j = 0; j < RANK; j++) {
            float4 v = B4[j * N4 + c];                 // coalesced LDG.128
            v.x *= LORA_SCALE; v.y *= LORA_SCALE; v.z *= LORA_SCALE; v.w *= LORA_SCALE;
            b2[ch][j][0] = pack2(v.x, v.y);
            b2[ch][j][1] = pack2(v.z, v.w);
        }
    }

    // ---------------- Phase 2: out = t @ (B*scale) ----------------------------
    for (int r = 0; r < nr; r++) {
        const float4 t0 = *reinterpret_cast<const float4*>(&s_t[r * RANK]);      // broadcast LDS
        const float4 t1 = *reinterpret_cast<const float4*>(&s_t[r * RANK + 4]);
        uint64_t ts[8];
        ts[0] = pack2(t0.x, t0.x); ts[1] = pack2(t0.y, t0.y);
        ts[2] = pack2(t0.z, t0.z); ts[3] = pack2(t0.w, t0.w);
        ts[4] = pack2(t1.x, t1.x); ts[5] = pack2(t1.y, t1.y);
        ts[6] = pack2(t1.z, t1.z); ts[7] = pack2(t1.w, t1.w);

        const size_t obase = (size_t)(r0 + r) * N4;
#pragma unroll
        for (int ch = 0; ch < 2; ch++) {
            uint64_t oA = 0ull, oB = 0ull;
#pragma unroll
            for (int j = 0; j < RANK; j++) {
                oA = fma2(ts[j], b2[ch][j][0], oA);
                oB = fma2(ts[j], b2[ch][j][1], oB);
            }
            float4 o;
            unpack2(oA, o.x, o.y);
            unpack2(oB, o.z, o.w);
            out4[obase + (ch ? c1 : c0)] = o;          // coalesced STG.128
        }
    }
}

extern "C" void kernel_launch(void* const* d_in, const int* in_sizes, int n_in,
                              void* d_out, int out_size)
{
    const float4* x4 = (const float4*)d_in[0];   // [4,2048,4096]
    const float4* A4 = (const float4*)d_in[1];   // [4096,8]
    const float4* B4 = (const float4*)d_in[2];   // [8,4096]
    float4* out4 = (float4*)d_out;

    const int K    = in_sizes[1] / RANK;         // 4096
    const int rows = in_sizes[0] / K;            // 8192

    int sms = 148;
    cudaDeviceGetAttribute(&sms, cudaDevAttrMultiProcessorCount, 0);

    lora_fused_kernel<<<sms, THREADS>>>(x4, A4, B4, out4, rows, sms);
}

// round 3
// speedup vs baseline: 2.1425x; 1.1126x over previous
#include <cuda_runtime.h>
#include <cstdint>

#define THREADS 512
#define RANK 8
#define K4 1024            // K/4
#define N4 1024            // N/4
#define MAXROWS 64
#define RB 4               // rows per phase-1 batch
#define LORA_SCALE 2.0f    // alpha/r = 16/8

// ---- packed f32x2 helpers (FFMA2 only reachable via PTX) ----
__device__ __forceinline__ uint64_t pack2(float lo, float hi) {
    uint64_t r; asm("mov.b64 %0, {%1, %2};" : "=l"(r) : "f"(lo), "f"(hi)); return r;
}
__device__ __forceinline__ void unpack2(uint64_t v, float& lo, float& hi) {
    asm("mov.b64 {%0, %1}, %2;" : "=f"(lo), "=f"(hi) : "l"(v));
}
__device__ __forceinline__ uint64_t fma2(uint64_t a, uint64_t b, uint64_t c) {
    uint64_t d; asm("fma.rn.f32x2 %0, %1, %2, %3;" : "=l"(d) : "l"(a), "l"(b), "l"(c)); return d;
}

__global__ __launch_bounds__(THREADS, 1)
void lora_fused_kernel(const float4* __restrict__ x4,
                       const float4* __restrict__ A4,
                       const float4* __restrict__ B4,
                       float4* __restrict__ out4,
                       int rows, int grid)
{
    __shared__ float s_part[MAXROWS * 128];   // [row][warp16][j8]
    __shared__ float s_t[MAXROWS * RANK];

    const int tid  = threadIdx.x;
    const int lane = tid & 31;
    const int warp = tid >> 5;

    const int r0 = (int)((long)blockIdx.x * rows / grid);
    const int r1 = (int)((long)(blockIdx.x + 1) * rows / grid);
    const int nr = r1 - r0;                   // <= MAXROWS

    const int c0 = tid;
    const int c1 = tid + THREADS;

    // ---------------- A cache: 2 chunks x 4 k x 4 j-pairs --------------------
    uint64_t a2[2][4][4];
#pragma unroll
    for (int ch = 0; ch < 2; ch++) {
        const int c = ch ? c1 : c0;
#pragma unroll
        for (int kk = 0; kk < 4; kk++) {
            float4 lo = A4[c * 8 + kk * 2];
            float4 hi = A4[c * 8 + kk * 2 + 1];
            a2[ch][kk][0] = pack2(lo.x, lo.y);
            a2[ch][kk][1] = pack2(lo.z, lo.w);
            a2[ch][kk][2] = pack2(hi.x, hi.y);
            a2[ch][kk][3] = pack2(hi.z, hi.w);
        }
    }

    // ---------------- Phase 1: t = x@A, 4 rows per batch ----------------------
    const int j_mine = ((lane >> 4) & 1) * 4 + ((lane >> 3) & 1) * 2 + ((lane >> 2) & 1);
    const bool write_lane = (lane & 3) == 0;

    for (int rb = 0; rb < nr; rb += RB) {
        uint64_t p2[RB][4];
#pragma unroll
        for (int r = 0; r < RB; r++)
#pragma unroll
            for (int jp = 0; jp < 4; jp++) p2[r][jp] = 0ull;

#pragma unroll
        for (int ch = 0; ch < 2; ch++) {
            const int c = ch ? c1 : c0;
            float4 xv[RB];
#pragma unroll
            for (int r = 0; r < RB; r++) {           // 4 back-to-back LDG.128
                int row = rb + r; row = (row < nr) ? row : (nr - 1);
                xv[r] = x4[(size_t)(r0 + row) * K4 + c];
            }
#pragma unroll
            for (int r = 0; r < RB; r++) {
                const float xc[4] = {xv[r].x, xv[r].y, xv[r].z, xv[r].w};
#pragma unroll
                for (int kk = 0; kk < 4; kk++) {
                    uint64_t xs = pack2(xc[kk], xc[kk]);
#pragma unroll
                    for (int jp = 0; jp < 4; jp++)
                        p2[r][jp] = fma2(xs, a2[ch][kk][jp], p2[r][jp]);
                }
            }
        }

        // Interleaved folding butterflies for the 4 rows (latencies overlap).
        const bool h  = (lane & 16) != 0;
        const bool qb = (lane & 8) != 0;
        const bool ob = (lane & 4) != 0;
#pragma unroll
        for (int r = 0; r < RB; r++) {
            float p[8];
#pragma unroll
            for (int jp = 0; jp < 4; jp++) unpack2(p2[r][jp], p[2 * jp], p[2 * jp + 1]);

            float q[4];
#pragma unroll
            for (int m = 0; m < 4; m++) {
                float send = h ? p[m] : p[m + 4];
                float keep = h ? p[m + 4] : p[m];
                q[m] = keep + __shfl_xor_sync(0xffffffffu, send, 16);
            }
            float u[2];
#pragma unroll
            for (int m = 0; m < 2; m++) {
                float send = qb ? q[m] : q[m + 2];
                float keep = qb ? q[m + 2] : q[m];
                u[m] = keep + __shfl_xor_sync(0xffffffffu, send, 8);
            }
            float send = ob ? u[0] : u[1];
            float keep = ob ? u[1] : u[0];
            float w = keep + __shfl_xor_sync(0xffffffffu, send, 4);
            w += __shfl_xor_sync(0xffffffffu, w, 2);
            w += __shfl_xor_sync(0xffffffffu, w, 1);
            if (write_lane && (rb + r) < nr)
                s_part[(rb + r) * 128 + warp * 8 + j_mine] = w;
        }
    }
    __syncthreads();

    // ---------------- Cross-warp reduce into s_t ------------------------------
    for (int i = tid; i < nr * RANK; i += THREADS) {
        const int row = i >> 3, j = i & 7;
        float s = 0.0f;
#pragma unroll
        for (int w = 0; w < 16; w++) s += s_part[row * 128 + w * 8 + j];
        s_t[i] = s;
    }
    __syncthreads();

    // ---------------- B cache: 2 chunks x 8 j x 2 n-pairs, pre-scaled ---------
    uint64_t b2[2][8][2];
#pragma unroll
    for (int ch = 0; ch < 2; ch++) {
        const int c = ch ? c1 : c0;
#pragma unroll
        for (int j = 0; j < RANK; j++) {
            float4 v = B4[j * N4 + c];
            v.x *= LORA_SCALE; v.y *= LORA_SCALE; v.z *= LORA_SCALE; v.w *= LORA_SCALE;
            b2[ch][j][0] = pack2(v.x, v.y);
            b2[ch][j][1] = pack2(v.z, v.w);
        }
    }

    // ---------------- Phase 2: out = t @ (B*scale) ----------------------------
    for (int r = 0; r < nr; r++) {
        const float4 t0 = *reinterpret_cast<const float4*>(&s_t[r * RANK]);
        const float4 t1 = *reinterpret_cast<const float4*>(&s_t[r * RANK + 4]);
        uint64_t ts[8];
        ts[0] = pack2(t0.x, t0.x); ts[1] = pack2(t0.y, t0.y);
        ts[2] = pack2(t0.z, t0.z); ts[3] = pack2(t0.w, t0.w);
        ts[4] = pack2(t1.x, t1.x); ts[5] = pack2(t1.y, t1.y);
        ts[6] = pack2(t1.z, t1.z); ts[7] = pack2(t1.w, t1.w);

        const size_t obase = (size_t)(r0 + r) * N4;
#pragma unroll
        for (int ch = 0; ch < 2; ch++) {
            uint64_t oA = 0ull, oB = 0ull;
#pragma unroll
            for (int j = 0; j < RANK; j++) {
                oA = fma2(ts[j], b2[ch][j][0], oA);
                oB = fma2(ts[j], b2[ch][j][1], oB);
            }
            float4 o;
            unpack2(oA, o.x, o.y);
            unpack2(oB, o.z, o.w);
            out4[obase + (ch ? c1 : c0)] = o;
        }
    }
}

extern "C" void kernel_launch(void* const* d_in, const int* in_sizes, int n_in,
                              void* d_out, int out_size)
{
    const float4* x4 = (const float4*)d_in[0];
    const float4* A4 = (const float4*)d_in[1];
    const float4* B4 = (const float4*)d_in[2];
    float4* out4 = (float4*)d_out;

    const int K    = in_sizes[1] / RANK;
    const int rows = in_sizes[0] / K;

    int sms = 148;
    cudaDeviceGetAttribute(&sms, cudaDevAttrMultiProcessorCount, 0);

    lora_fused_kernel<<<sms, THREADS>>>(x4, A4, B4, out4, rows, sms);
}